// round 11
// baseline (speedup 1.0000x reference)
#include <cuda_runtime.h>

// LogSpaceSinkhorn: 64 independent 1024x1024 fp32 matrices.
// Potentials form: ls = y - u_i - v_j, y = x*log2(e)/max(tau,0.1), base-2 log space.
// Fused row+col pass: per CTA stage t = 2^(y - v) for an 8x1024 tile in smem,
// row-reduce to u_i = log2(S_i), then column partials P_j = sum_i t_ij / S_i.
// v update: v'_j = v_j + log2(sum_blocks P_j). One matrix read per iteration
// instead of two. L2-resident chunks of 16 matrices (64MB << 126MB L2).

#define NN    1024
#define BMAX  64
#define CHUNK 16
#define RB    8              // rows per fused CTA
#define RBLK  (NN / RB)      // 128 row-blocks per matrix

static __device__ __align__(16) float g_u[BMAX * NN];
static __device__ __align__(16) float g_v[BMAX * NN];
static __device__ __align__(16) float g_P[CHUNK * RBLK * NN];   // 8 MB partials

__device__ __forceinline__ float ex2f(float x) {
    float y; asm("ex2.approx.ftz.f32 %0, %1;" : "=f"(y) : "f"(x)); return y;
}
__device__ __forceinline__ float lg2f(float x) {
    float y; asm("lg2.approx.ftz.f32 %0, %1;" : "=f"(y) : "f"(x)); return y;
}
__device__ __forceinline__ float rcpf(float x) {
    float y; asm("rcp.approx.ftz.f32 %0, %1;" : "=f"(y) : "f"(x)); return y;
}
__device__ __forceinline__ float get_scale(const float* __restrict__ tau) {
    return 1.4426950408889634f / fmaxf(*tau, 0.1f);   // log2(e)/max(tau,0.1)
}

// Fused pass: reads a once; writes u (g_u) and column partials (g_P).
// CTA = 256 threads = 8 warps; warp w owns row rb*8+w of the tile.
__global__ void __launch_bounds__(256) fused_pass(
    const float* __restrict__ a, const float* __restrict__ tau,
    int use_v, int mbase)
{
    __shared__ float tt[RB][NN];    // 32 KB t-tile
    __shared__ float sv[NN];        // 4 KB v
    __shared__ float sr[RB];        // 1/S per row

    int cta  = blockIdx.x;          // chunk-local: mi*RBLK + rb
    int mi   = cta >> 7;
    int rb   = cta & (RBLK - 1);
    int m    = mbase + mi;
    int tid  = threadIdx.x;
    int lane = tid & 31;
    int w    = tid >> 5;

    float scale = get_scale(tau);

    // stage v (or zeros on the first iteration)
    if (use_v)
        reinterpret_cast<float4*>(sv)[tid] =
            reinterpret_cast<const float4*>(g_v + (m << 10))[tid];
    else
        reinterpret_cast<float4*>(sv)[tid] = make_float4(0.f, 0.f, 0.f, 0.f);
    __syncthreads();

    // Phase A/B: warp per row — load y, compute t = 2^(y*scale - v), stage t,
    // accumulate row sum S.
    const float* __restrict__ arow =
        a + ((size_t)m << 20) + ((size_t)(rb * RB + w) << 10);
    float s = 0.f;
#pragma unroll
    for (int it = 0; it < 8; ++it) {
        int j = it * 128 + lane * 4;
        float4 av = *reinterpret_cast<const float4*>(arow + j);
        float4 vv = *reinterpret_cast<const float4*>(sv + j);
        float t0 = ex2f(fmaf(av.x, scale, -vv.x));
        float t1 = ex2f(fmaf(av.y, scale, -vv.y));
        float t2 = ex2f(fmaf(av.z, scale, -vv.z));
        float t3 = ex2f(fmaf(av.w, scale, -vv.w));
        s += (t0 + t1) + (t2 + t3);
        *reinterpret_cast<float4*>(&tt[w][j]) = make_float4(t0, t1, t2, t3);
    }
#pragma unroll
    for (int o = 16; o; o >>= 1) s += __shfl_xor_sync(0xffffffffu, s, o);
    if (lane == 0) {
        g_u[(m << 10) + rb * RB + w] = lg2f(s);
        sr[w] = rcpf(s);
    }
    __syncthreads();

    // Phase C: thread = column quad; P_j = sum_i t_ij * (1/S_i) over 8 rows.
    float4 p = make_float4(0.f, 0.f, 0.f, 0.f);
#pragma unroll
    for (int i = 0; i < RB; ++i) {
        float4 tv = *reinterpret_cast<const float4*>(&tt[i][tid * 4]);
        float ri = sr[i];
        p.x = fmaf(tv.x, ri, p.x);
        p.y = fmaf(tv.y, ri, p.y);
        p.z = fmaf(tv.z, ri, p.z);
        p.w = fmaf(tv.w, ri, p.w);
    }
    *reinterpret_cast<float4*>(&g_P[((mi * RBLK + rb) << 10) + tid * 4]) = p;
}

// v update: v_j <- (add ? v_j : 0) + c * log2( sum_rb P[rb][j] ).
// c = 1 normally; c = 0.5 for the symmetric-final blend (w = v5 + 0.5*lg2(sumP6)).
__global__ void __launch_bounds__(256) vsum_k(float c, int add, int mbase)
{
    int t  = blockIdx.x * 256 + threadIdx.x;   // chunk-local: mi*1024 + j
    int mi = t >> 10;
    int j  = t & 1023;

    const float* __restrict__ p = g_P + ((mi * RBLK) << 10) + j;
    float s = 0.f;
#pragma unroll 8
    for (int rb = 0; rb < RBLK; ++rb) s += p[(size_t)rb << 10];

    int o = ((mbase + mi) << 10) + j;
    float base = add ? g_v[o] : 0.f;
    g_v[o] = fmaf(c, lg2f(s), base);
}

// out_ij = 2^(y*scale - u6_i - w_j); w already blended into g_v.
__global__ void __launch_bounds__(256) finalize_k(
    const float* __restrict__ a, const float* __restrict__ tau,
    float* __restrict__ out, int mbase)
{
    size_t e = ((size_t)(blockIdx.x * blockDim.x + threadIdx.x) << 2)
             + ((size_t)mbase << 20);
    int m   = (int)(e >> 20);
    int row = (int)(e >> 10) & 1023;
    int j   = (int)(e & 1023);

    float scale = get_scale(tau);
    float uv = g_u[(m << 10) + row];
    float4 wv = *reinterpret_cast<const float4*>(&g_v[(m << 10) + j]);
    float4 av = *reinterpret_cast<const float4*>(a + e);

    float4 r;
    r.x = ex2f(fmaf(av.x, scale, -(uv + wv.x)));
    r.y = ex2f(fmaf(av.y, scale, -(uv + wv.y)));
    r.z = ex2f(fmaf(av.z, scale, -(uv + wv.z)));
    r.w = ex2f(fmaf(av.w, scale, -(uv + wv.w)));
    *reinterpret_cast<float4*>(out + e) = r;
}

extern "C" void kernel_launch(void* const* d_in, const int* in_sizes, int n_in,
                              void* d_out, int out_size)
{
    const float* a   = (const float*)d_in[0];
    const float* tau = (const float*)d_in[1];
    float* out       = (float*)d_out;

    int b = in_sizes[0] / (NN * NN);          // 64 matrices

    for (int c0 = 0; c0 < b; c0 += CHUNK) {
        int nm = (b - c0 < CHUNK) ? (b - c0) : CHUNK;
        dim3 fg(nm * RBLK), fb(256);          // fused: 128 CTAs per matrix
        dim3 vg(nm * NN / 256), vb(256);      // vsum: 1 thread per column
        dim3 og(nm * 1024), ob(256);          // finalize: nm*1M elems / 4 / 256

        // Iterations 1..5: u_k, v_k  (v_0 = 0)
        for (int it = 0; it < 5; ++it) {
            fused_pass<<<fg, fb>>>(a, tau, it > 0, c0);
            vsum_k<<<vg, vb>>>(1.0f, it > 0, c0);
        }
        // Symmetric final: fused #6 yields u6 and P6 (w.r.t. v5);
        // w = v5 + 0.5*log2(sum P6) = 0.5*(v5 + v6)
        fused_pass<<<fg, fb>>>(a, tau, 1, c0);
        vsum_k<<<vg, vb>>>(0.5f, 1, c0);
        // out = 2^(y - u6 - w), chunk still L2-hot
        finalize_k<<<og, ob>>>(a, tau, out, c0);
    }
}

// round 12
// speedup vs baseline: 1.8563x; 1.8563x over previous
#include <cuda_runtime.h>

// LogSpaceSinkhorn: 64 independent 1024x1024 fp32 matrices.
// ls = y - u_i - v_j with y = x*log2(e)/max(tau,0.1), all base-2 log space.
// Fused row+col pass: t = 2^(y - v) staged in smem 8 rows at a time,
// u_i = lg2(S_i), column partials P_j = sum_i t_ij/S_i; v' = v + lg2(sum P).
// 7 matrix reads per chunk (6 fused + finalize) instead of 13.
// L2-resident chunks of 16 matrices (64MB << 126MB L2).

#define NN    1024
#define BMAX  64
#define CHUNK 16
#define RB    8               // rows per sub-tile
#define SUBS  4               // sub-tiles per CTA -> 32 rows per CTA
#define RBLK  (NN / (RB * SUBS))   // 32 row-blocks per matrix

static __device__ __align__(16) float g_u[BMAX * NN];
static __device__ __align__(16) float g_v[BMAX * NN];
static __device__ __align__(16) float g_P[CHUNK * RBLK * NN];   // 2 MB partials

__device__ __forceinline__ float ex2f(float x) {
    float y; asm("ex2.approx.ftz.f32 %0, %1;" : "=f"(y) : "f"(x)); return y;
}
__device__ __forceinline__ float lg2f(float x) {
    float y; asm("lg2.approx.ftz.f32 %0, %1;" : "=f"(y) : "f"(x)); return y;
}
__device__ __forceinline__ float rcpf(float x) {
    float y; asm("rcp.approx.ftz.f32 %0, %1;" : "=f"(y) : "f"(x)); return y;
}
__device__ __forceinline__ float get_scale(const float* __restrict__ tau) {
    return 1.4426950408889634f / fmaxf(*tau, 0.1f);   // log2(e)/max(tau,0.1)
}

// Fused pass: one matrix read -> u rows + column partials P.
// CTA = 256 threads = 8 warps; owns 32 consecutive rows (4 sub-tiles of 8).
__global__ void __launch_bounds__(256) fused_pass(
    const float* __restrict__ a, const float* __restrict__ tau,
    int use_v, int mbase)
{
    __shared__ float tt[RB][NN];    // 32 KB t-tile
    __shared__ float sv[NN];        // 4 KB v
    __shared__ float sr[RB];        // 1/S per staged row

    int cta  = blockIdx.x;                    // chunk-local: mi*RBLK + rb
    int mi   = cta >> 5;
    int rb   = cta & (RBLK - 1);
    int m    = mbase + mi;
    int tid  = threadIdx.x;
    int lane = tid & 31;
    int w    = tid >> 5;

    float scale = get_scale(tau);

    if (use_v)
        reinterpret_cast<float4*>(sv)[tid] =
            reinterpret_cast<const float4*>(g_v + (m << 10))[tid];
    else
        reinterpret_cast<float4*>(sv)[tid] = make_float4(0.f, 0.f, 0.f, 0.f);
    __syncthreads();

    float4 p = make_float4(0.f, 0.f, 0.f, 0.f);

#pragma unroll
    for (int sub = 0; sub < SUBS; ++sub) {
        // Phase A: warp per row — t = 2^(y*scale - v), stage in smem, row sum.
        int row = rb * (RB * SUBS) + sub * RB + w;
        const float* __restrict__ arow = a + ((size_t)m << 20) + ((size_t)row << 10);
        float s = 0.f;
#pragma unroll
        for (int it = 0; it < 8; ++it) {
            int j = it * 128 + lane * 4;
            float4 av = *reinterpret_cast<const float4*>(arow + j);
            float4 vv = *reinterpret_cast<const float4*>(sv + j);
            float t0 = ex2f(fmaf(av.x, scale, -vv.x));
            float t1 = ex2f(fmaf(av.y, scale, -vv.y));
            float t2 = ex2f(fmaf(av.z, scale, -vv.z));
            float t3 = ex2f(fmaf(av.w, scale, -vv.w));
            s += (t0 + t1) + (t2 + t3);
            *reinterpret_cast<float4*>(&tt[w][j]) = make_float4(t0, t1, t2, t3);
        }
#pragma unroll
        for (int o = 16; o; o >>= 1) s += __shfl_xor_sync(0xffffffffu, s, o);
        if (lane == 0) {
            g_u[(m << 10) + row] = lg2f(s);
            sr[w] = rcpf(s);
        }
        __syncthreads();

        // Phase C: thread per column quad — accumulate t/S over the 8 rows.
        float4 acc = p;
#pragma unroll
        for (int i = 0; i < RB; ++i) {
            float4 tv = *reinterpret_cast<const float4*>(&tt[i][tid * 4]);
            float ri = sr[i];
            acc.x = fmaf(tv.x, ri, acc.x);
            acc.y = fmaf(tv.y, ri, acc.y);
            acc.z = fmaf(tv.z, ri, acc.z);
            acc.w = fmaf(tv.w, ri, acc.w);
        }
        p = acc;
        __syncthreads();   // protect tt/sr before next sub-tile overwrites
    }

    *reinterpret_cast<float4*>(&g_P[((mi * RBLK + rb) << 10) + tid * 4]) = p;
}

// v update: v_j <- (add ? v_j : 0) + c * lg2( sum_rb P[rb][j] ), 32 rb values.
// CTA = 256 threads: 64 columns x 4 rb-quarters, coalesced, smem reduce.
// grid = nm*16.
__global__ void __launch_bounds__(256) vsum_k(float c, int add, int mbase)
{
    __shared__ float red[4][64];

    int mi = blockIdx.x >> 4;
    int cb = (blockIdx.x & 15) << 6;     // 64-column block
    int t  = threadIdx.x;
    int j  = cb + (t & 63);
    int q  = t >> 6;                      // rb quarter 0..3

    const float* __restrict__ p = g_P + ((mi * RBLK + q * 8) << 10) + j;
    float s = 0.f;
#pragma unroll
    for (int r = 0; r < 8; ++r) s += p[(size_t)r << 10];
    red[q][t & 63] = s;
    __syncthreads();

    if (t < 64) {
        float total = (red[0][t] + red[1][t]) + (red[2][t] + red[3][t]);
        int o = ((mbase + mi) << 10) + cb + t;
        float base = add ? g_v[o] : 0.f;
        g_v[o] = fmaf(c, lg2f(total), base);
    }
}

// out_ij = 2^(y*scale - u6_i - w_j); w = 0.5*(v5+v6) already blended into g_v.
__global__ void __launch_bounds__(256) finalize_k(
    const float* __restrict__ a, const float* __restrict__ tau,
    float* __restrict__ out, int mbase)
{
    size_t e = ((size_t)(blockIdx.x * blockDim.x + threadIdx.x) << 2)
             + ((size_t)mbase << 20);
    int m   = (int)(e >> 20);
    int row = (int)(e >> 10) & 1023;
    int j   = (int)(e & 1023);

    float scale = get_scale(tau);
    float uv = g_u[(m << 10) + row];
    float4 wv = *reinterpret_cast<const float4*>(&g_v[(m << 10) + j]);
    float4 av = *reinterpret_cast<const float4*>(a + e);

    float4 r;
    r.x = ex2f(fmaf(av.x, scale, -(uv + wv.x)));
    r.y = ex2f(fmaf(av.y, scale, -(uv + wv.y)));
    r.z = ex2f(fmaf(av.z, scale, -(uv + wv.z)));
    r.w = ex2f(fmaf(av.w, scale, -(uv + wv.w)));
    *reinterpret_cast<float4*>(out + e) = r;
}

extern "C" void kernel_launch(void* const* d_in, const int* in_sizes, int n_in,
                              void* d_out, int out_size)
{
    const float* a   = (const float*)d_in[0];
    const float* tau = (const float*)d_in[1];
    float* out       = (float*)d_out;

    int b = in_sizes[0] / (NN * NN);          // 64 matrices

    for (int c0 = 0; c0 < b; c0 += CHUNK) {
        int nm = (b - c0 < CHUNK) ? (b - c0) : CHUNK;
        dim3 fg(nm * RBLK), fb(256);          // fused: 32 CTAs per matrix
        dim3 vg(nm * 16),   vb(256);          // vsum:  16 CTAs per matrix
        dim3 og(nm * 1024), ob(256);          // finalize

        // Iterations 1..5: u_k then v_k (v_0 = 0)
        for (int it = 0; it < 5; ++it) {
            fused_pass<<<fg, fb>>>(a, tau, it > 0, c0);
            vsum_k<<<vg, vb>>>(1.0f, it > 0, c0);
        }
        // Symmetric final: fused #6 gives u6 and P6 (w.r.t. v5);
        // w = v5 + 0.5*lg2(sum P6) = 0.5*(v5 + v6)
        fused_pass<<<fg, fb>>>(a, tau, 1, c0);
        vsum_k<<<vg, vb>>>(0.5f, 1, c0);
        // out = 2^(y - u6 - w), chunk still L2-hot
        finalize_k<<<og, ob>>>(a, tau, out, c0);
    }
}